// round 14
// baseline (speedup 1.0000x reference)
#include <cuda_runtime.h>
#include <cuda_fp16.h>
#include <math.h>

// ---------------- problem constants ----------------
#define MAXN   100000
#define MAXE   1600000
#define MAXG   128
#define FIN    12
#define HROW   16                 // fp16 chain row: 16 halves = 32B
#define NT     9                  // matmul terms: x, To1..4, Ti1..4
#define WCSZ   (NT * FIN * 64)    // combined weights (Z|H stacked on 64)
#define PADE   (MAXE + 4 * MAXN)  // padded edge-list bound
#define HRSZ   ((size_t)(MAXN + 1) * HROW)   // fp16 chain row block (+ sentinel)

// ---------------- device scratch (static, no allocs) ----------------
__device__ float2 d_dcout[MAXN];  // {weighted out-degree, out-count(float)}
__device__ float2 d_dcin[MAXN];   // {weighted in-degree,  in-count(float)}
__device__ float  d_doi[MAXN], d_dii[MAXN];
__device__ int    d_cnt_in[MAXN], d_cnt_out[MAXN];
__device__ int    d_off_in[MAXN], d_off_out[MAXN];
__device__ int    d_ctr_in, d_ctr_out;       // global bump allocators
__device__ int    d_rank_in[MAXE], d_rank_out[MAXE];
__device__ int    d_csc[PADE];    // grouped by dst: src indices  (fwd gather)
__device__ int    d_csr[PADE];    // grouped by src: dst indices  (rev gather)
__device__ __half d_hXp[HRSZ];    // fp16 x (+ zero sentinel row MAXN)
__device__ __half d_hS[5][HRSZ];  // fp16 scaled fwd chain S0..S4
__device__ __half d_hTi[4][HRSZ]; // fp16 rev chain Ti1..Ti4
__device__ float  d_Wc[WCSZ];
__device__ float  d_gsum[MAXG * 4];
__device__ float  d_gcnt[MAXG];

// ---------------- helpers ----------------
// vector atomic add WITH return: accumulates {deg, cnt} and yields old values
// (old cnt == this edge's rank within its node segment)
__device__ __forceinline__ float2 atom_add2_ret(float2* p, float a, float b) {
    float2 r;
    asm volatile("atom.global.add.v2.f32 {%0, %1}, [%2], {%3, %4};"
                 : "=f"(r.x), "=f"(r.y)
                 : "l"(__cvta_generic_to_global(p)), "f"(a), "f"(b)
                 : "memory");
    return r;
}

__device__ __forceinline__ void store_h_row(__half* hdst, int n, const float* v) {
    __half2 h0 = __floats2half2_rn(v[0], v[1]);
    __half2 h1 = __floats2half2_rn(v[2], v[3]);
    __half2 h2 = __floats2half2_rn(v[4], v[5]);
    __half2 h3 = __floats2half2_rn(v[6], v[7]);
    __half2 h4 = __floats2half2_rn(v[8], v[9]);
    __half2 h5 = __floats2half2_rn(v[10], v[11]);
    __half2 zz = __floats2half2_rn(0.f, 0.f);
    uint4 u0, u1;
    u0.x = *(unsigned*)&h0; u0.y = *(unsigned*)&h1; u0.z = *(unsigned*)&h2; u0.w = *(unsigned*)&h3;
    u1.x = *(unsigned*)&h4; u1.y = *(unsigned*)&h5; u1.z = *(unsigned*)&zz; u1.w = *(unsigned*)&zz;
    uint4* p = (uint4*)(hdst + (size_t)n * HROW);
    p[0] = u0; p[1] = u1;
}

// ---------------- kernels ----------------

// zero accumulators + fp16 sentinel rows + build combined weights (all fused)
__global__ void init_wc_kernel(const float* __restrict__ Wz, const float* __restrict__ Wh,
                               int Nn, int Gg) {
    int i = blockIdx.x * blockDim.x + threadIdx.x;
    if (i == 0) { d_ctr_in = 0; d_ctr_out = 0; }
    if (i < Nn) {
        d_dcout[i] = make_float2(0.f, 0.f);
        d_dcin[i]  = make_float2(0.f, 0.f);
    }
    if (i < Gg * 4) d_gsum[i] = 0.f;
    if (i < Gg)     d_gcnt[i] = 0.f;
    if (i < HROW) {                // zero fp16 sentinel rows (index MAXN)
        __half z = __float2half(0.f);
        d_hXp[(size_t)MAXN * HROW + i] = z;
#pragma unroll
        for (int k = 0; k < 5; k++) d_hS[k][(size_t)MAXN * HROW + i] = z;
#pragma unroll
        for (int k = 0; k < 4; k++) d_hTi[k][(size_t)MAXN * HROW + i] = z;
    }
    if (i < WCSZ) {
        int f2 = i & 63;
        int j  = (i >> 6) % FIN;
        int t  = i / (FIN * 64);
        const float* W = (f2 < 32) ? Wz : Wh;
        int f = f2 & 31;
        float v;
        if (t == 0)      v = W[0 * 1408 + j * 32 + f] + W[5 * 1408 + j * 32 + f];
        else if (t <= 4) v = W[(0 * 5 + t) * 1408 + j * 32 + f];
        else             v = W[(1 * 5 + (t - 4)) * 1408 + j * 32 + f];
        d_Wc[i] = v;
    }
}

// weighted degrees + counts + per-edge ranks in ONE vector atomic per
// edge-direction (2 L2 atomic ops per edge, total). 2 edges per thread.
__global__ void degrees_rank_kernel(const int* __restrict__ row, const int* __restrict__ col,
                                    const float* __restrict__ w, int E) {
    int t = blockIdx.x * blockDim.x + threadIdx.x;
    int e = t * 2;
    if (e + 1 < E) {
        int2   ss = *(const int2*)(row + e);
        int2   dd = *(const int2*)(col + e);
        float2 ww = *(const float2*)(w + e);
        float2 ro0 = atom_add2_ret(&d_dcout[ss.x], ww.x, 1.f);
        float2 ro1 = atom_add2_ret(&d_dcout[ss.y], ww.y, 1.f);
        float2 ri0 = atom_add2_ret(&d_dcin[dd.x],  ww.x, 1.f);
        float2 ri1 = atom_add2_ret(&d_dcin[dd.y],  ww.y, 1.f);
        *(int2*)(d_rank_in + e)  = make_int2(__float2int_rn(ri0.y), __float2int_rn(ri1.y));
        *(int2*)(d_rank_out + e) = make_int2(__float2int_rn(ro0.y), __float2int_rn(ro1.y));
    } else if (e < E) {
        int s = row[e], d = col[e];
        float we = w[e];
        float2 ro = atom_add2_ret(&d_dcout[s], we, 1.f);
        float2 ri = atom_add2_ret(&d_dcin[d],  we, 1.f);
        d_rank_in[e]  = __float2int_rn(ri.y);
        d_rank_out[e] = __float2int_rn(ro.y);
    }
}

// fused: per-node prep (inv degrees, fp16 x, fp16 S0) + CSR segment allocation
// via warp-aggregated atomic bump + sentinel padding (region disjoint from fill)
__global__ void prep_alloc_kernel(const float* __restrict__ x, int Nn) {
    int i = blockIdx.x * blockDim.x + threadIdx.x;
    int lane = threadIdx.x & 31;

    int ci = 0, co = 0;
    float degi = 1.f, dego = 1.f;
    if (i < Nn) {
        float2 din = d_dcin[i];
        float2 dou = d_dcout[i];
        ci = __float2int_rn(din.y);
        co = __float2int_rn(dou.y);
        degi = din.x;
        dego = dou.x;
    }
    int pi = (ci + 3) & ~3;
    int po = (co + 3) & ~3;

    // warp-inclusive scan of padded counts
    int inc_i = pi, inc_o = po;
#pragma unroll
    for (int s = 1; s < 32; s <<= 1) {
        int vi = __shfl_up_sync(0xffffffffu, inc_i, s);
        int vo = __shfl_up_sync(0xffffffffu, inc_o, s);
        if (lane >= s) { inc_i += vi; inc_o += vo; }
    }
    int tot_i = __shfl_sync(0xffffffffu, inc_i, 31);
    int tot_o = __shfl_sync(0xffffffffu, inc_o, 31);
    int base_i = 0, base_o = 0;
    if (lane == 0) {
        base_i = atomicAdd(&d_ctr_in, tot_i);
        base_o = atomicAdd(&d_ctr_out, tot_o);
    }
    base_i = __shfl_sync(0xffffffffu, base_i, 0);
    base_o = __shfl_sync(0xffffffffu, base_o, 0);

    if (i < Nn) {
        int oi = base_i + inc_i - pi;
        int oo = base_o + inc_o - po;
        d_off_in[i] = oi;  d_cnt_in[i] = ci;
        d_off_out[i] = oo; d_cnt_out[i] = co;

        // sentinel padding: [off+cnt, off+pad) never touched by fill
        for (int k = ci; k < pi; k++) d_csc[oi + k] = MAXN;
        for (int k = co; k < po; k++) d_csr[oo + k] = MAXN;

        float doi = 1.0f / dego;
        float dii = 1.0f / degi;
        d_doi[i] = doi; d_dii[i] = dii;

        float v[FIN], s0[FIN];
        const float4* xr = (const float4*)(x + (size_t)i * FIN);
        float4 a = xr[0], b = xr[1], c = xr[2];
        v[0]=a.x; v[1]=a.y; v[2]=a.z; v[3]=a.w;
        v[4]=b.x; v[5]=b.y; v[6]=b.z; v[7]=b.w;
        v[8]=c.x; v[9]=c.y; v[10]=c.z; v[11]=c.w;
#pragma unroll
        for (int j = 0; j < FIN; j++) s0[j] = v[j] * doi;
        store_h_row(d_hXp, i, v);
        store_h_row(d_hS[0], i, s0);
    }
}

// CSR/CSC fill with precomputed ranks — NO atomics: coalesced idx/rank loads,
// L2-cached off gathers, scattered stores only. 2 edges per thread.
__global__ void fill_kernel(const int* __restrict__ row, const int* __restrict__ col,
                            int E) {
    int t = blockIdx.x * blockDim.x + threadIdx.x;
    int e = t * 2;
    if (e + 1 < E) {
        int2 ss = *(const int2*)(row + e);
        int2 dd = *(const int2*)(col + e);
        int2 ri = *(const int2*)(d_rank_in + e);
        int2 ro = *(const int2*)(d_rank_out + e);
        int p0 = d_off_in[dd.x] + ri.x;
        int p1 = d_off_in[dd.y] + ri.y;
        int q0 = d_off_out[ss.x] + ro.x;
        int q1 = d_off_out[ss.y] + ro.y;
        d_csc[p0] = ss.x;
        d_csc[p1] = ss.y;
        d_csr[q0] = dd.x;
        d_csr[q1] = dd.y;
    } else if (e < E) {
        int s = row[e], d = col[e];
        d_csc[d_off_in[d] + d_rank_in[e]] = s;
        d_csr[d_off_out[s] + d_rank_out[e]] = d;
    }
}

// one gather HALF (2 threads per node-dir, shfl-free): thread handles 16B half
// h of its node's row; pair lanes coalesce both halves of each 32B neighbor
// row into ONE wavefront. out_half = fac*diag*sum(neighbor halves) - prev_half.
__device__ __forceinline__ void gather_half(
    int n, int h, const int* __restrict__ idxbuf,
    const int* __restrict__ off, const int* __restrict__ cnt,
    const float* __restrict__ diag,
    const __half* __restrict__ hsrc, const __half* __restrict__ hprev,
    __half* __restrict__ hdst, float fac)
{
    __half2 a0, a1, a2, a3;
    __half2 hz = __floats2half2_rn(0.f, 0.f);
    a0 = hz; a1 = hz; a2 = hz; a3 = hz;

    const __half* src_h = hsrc + h * 8;   // this thread's 16B half offset

    int b = off[n];
    int e = b + ((cnt[n] + 3) & ~3);
    int i = b;
#define H2(u) (*reinterpret_cast<const __half2*>(&(u)))
#define ACC(U) { a0 = __hadd2(a0, H2((U).x)); a1 = __hadd2(a1, H2((U).y)); \
                 a2 = __hadd2(a2, H2((U).z)); a3 = __hadd2(a3, H2((U).w)); }
    for (; i + 8 <= e; i += 8) {
        int4 qa = *(const int4*)(idxbuf + i);
        int4 qb = *(const int4*)(idxbuf + i + 4);
        uint4 A = *(const uint4*)(src_h + (size_t)qa.x * HROW);
        uint4 B = *(const uint4*)(src_h + (size_t)qa.y * HROW);
        uint4 C = *(const uint4*)(src_h + (size_t)qa.z * HROW);
        uint4 D = *(const uint4*)(src_h + (size_t)qa.w * HROW);
        uint4 Ee = *(const uint4*)(src_h + (size_t)qb.x * HROW);
        uint4 F = *(const uint4*)(src_h + (size_t)qb.y * HROW);
        uint4 G = *(const uint4*)(src_h + (size_t)qb.z * HROW);
        uint4 Hh = *(const uint4*)(src_h + (size_t)qb.w * HROW);
        ACC(A) ACC(B) ACC(C) ACC(D) ACC(Ee) ACC(F) ACC(G) ACC(Hh)
    }
    if (i < e) {
        int4 qa = *(const int4*)(idxbuf + i);
        uint4 A = *(const uint4*)(src_h + (size_t)qa.x * HROW);
        uint4 B = *(const uint4*)(src_h + (size_t)qa.y * HROW);
        uint4 C = *(const uint4*)(src_h + (size_t)qa.z * HROW);
        uint4 D = *(const uint4*)(src_h + (size_t)qa.w * HROW);
        ACC(A) ACC(B) ACC(C) ACC(D)
    }
#undef ACC

    float c = diag[n] * fac;
    float2 f0 = __half22float2(a0);
    float2 f1 = __half22float2(a1);
    float2 f2 = __half22float2(a2);
    float2 f3 = __half22float2(a3);
    f0.x *= c; f0.y *= c; f1.x *= c; f1.y *= c;
    f2.x *= c; f2.y *= c; f3.x *= c; f3.y *= c;
    if (hprev) {
        uint4 pu = *(const uint4*)(hprev + (size_t)n * HROW + h * 8);
        float2 p0 = __half22float2(H2(pu.x));
        float2 p1 = __half22float2(H2(pu.y));
        float2 p2 = __half22float2(H2(pu.z));
        float2 p3 = __half22float2(H2(pu.w));
        f0.x -= p0.x; f0.y -= p0.y; f1.x -= p1.x; f1.y -= p1.y;
        f2.x -= p2.x; f2.y -= p2.y; f3.x -= p3.x; f3.y -= p3.y;
    }
#undef H2
    __half2 o0 = __floats2half2_rn(f0.x, f0.y);
    __half2 o1 = __floats2half2_rn(f1.x, f1.y);
    __half2 o2 = __floats2half2_rn(f2.x, f2.y);
    __half2 o3 = __floats2half2_rn(f3.x, f3.y);
    uint4 ou;
    ou.x = *(unsigned*)&o0; ou.y = *(unsigned*)&o1;
    ou.z = *(unsigned*)&o2; ou.w = *(unsigned*)&o3;
    *(uint4*)(hdst + (size_t)n * HROW + h * 8) = ou;
    // pad halves (features 12..15) stay zero inductively: sources are zero,
    // prev pad is zero, so h=1 writes c*0-0=0 there.
}

// one Chebyshev step, both chains; 2 threads per node-dir:
// threads [0,2N) fwd (n=tid/2, h=tid&1), [2N,4N) rev.
__global__ __launch_bounds__(256) void gprop_kernel(
    const __half* __restrict__ hsF, const __half* __restrict__ hpF, __half* __restrict__ hdF,
    const __half* __restrict__ hsR, const __half* __restrict__ hpR, __half* __restrict__ hdR,
    float fac, int Nn)
{
    int tid = blockIdx.x * blockDim.x + threadIdx.x;
    int h = tid & 1;
    int k = tid >> 1;
    if (k < Nn) {
        gather_half(k, h, d_csc, d_off_in, d_cnt_in, d_doi, hsF, hpF, hdF, fac);
    } else if (k < 2 * Nn) {
        gather_half(k - Nn, h, d_csr, d_off_out, d_cnt_out, d_dii, hsR, hpR, hdR, fac);
    }
}

// fused: H = x@Wc0 + sum_k (dout*S_k)@Wc_k + sum_k Ti_k@Wc_{4+k} (fp16 chains),
// then GRU gate (zero hidden) + relu + 32x4 linear + warp-aggregated mean-pool.
__global__ __launch_bounds__(128) void matmul_gate_pool_kernel(
    const float* __restrict__ x, const int* __restrict__ batch,
    const float* __restrict__ bz, const float* __restrict__ bh,
    const float* __restrict__ Wl, int Nn)
{
    __shared__ float sWc[WCSZ];
    __shared__ float sBz[32], sBh[32], sWl[128];
    for (int i = threadIdx.x; i < WCSZ; i += blockDim.x) sWc[i] = d_Wc[i];
    if (threadIdx.x < 32)  sBz[threadIdx.x] = bz[threadIdx.x];
    else if (threadIdx.x < 64) sBh[threadIdx.x - 32] = bh[threadIdx.x - 32];
    if (threadIdx.x < 128) sWl[threadIdx.x] = Wl[threadIdx.x];
    __syncthreads();

    int n = blockIdx.x * blockDim.x + threadIdx.x;
    float y0 = 0.f, y1 = 0.f, y2 = 0.f, y3 = 0.f, cntv = 0.f;
    int g = -1;

    if (n < Nn) {
        g = batch[n];
        cntv = 1.f;
        float dout = d_dcout[n].x;

        unsigned long long acc[32];
#pragma unroll
        for (int p = 0; p < 32; p++) acc[p] = 0ULL;

#pragma unroll 1
        for (int t = 0; t < NT; t++) {
            float vv[FIN];
            if (t == 0) {
                const float4* src = (const float4*)(x + (size_t)n * FIN);
                float4 v0 = src[0], v1 = src[1], v2 = src[2];
                vv[0]=v0.x; vv[1]=v0.y; vv[2]=v0.z; vv[3]=v0.w;
                vv[4]=v1.x; vv[5]=v1.y; vv[6]=v1.z; vv[7]=v1.w;
                vv[8]=v2.x; vv[9]=v2.y; vv[10]=v2.z; vv[11]=v2.w;
            } else {
                const __half* hr = ((t <= 4) ? d_hS[t] : d_hTi[t - 5]) + (size_t)n * HROW;
                float scale = (t <= 4) ? dout : 1.0f;
                const uint4* pp = (const uint4*)hr;
                uint4 u0 = pp[0], u1 = pp[1];
#define H2(u) (*reinterpret_cast<const __half2*>(&(u)))
                float2 f0 = __half22float2(H2(u0.x));
                float2 f1 = __half22float2(H2(u0.y));
                float2 f2 = __half22float2(H2(u0.z));
                float2 f3 = __half22float2(H2(u0.w));
                float2 f4 = __half22float2(H2(u1.x));
                float2 f5 = __half22float2(H2(u1.y));
#undef H2
                vv[0]=f0.x*scale; vv[1]=f0.y*scale; vv[2]=f1.x*scale;  vv[3]=f1.y*scale;
                vv[4]=f2.x*scale; vv[5]=f2.y*scale; vv[6]=f3.x*scale;  vv[7]=f3.y*scale;
                vv[8]=f4.x*scale; vv[9]=f4.y*scale; vv[10]=f5.x*scale; vv[11]=f5.y*scale;
            }
#pragma unroll
            for (int j = 0; j < FIN; j++) {
                unsigned long long tv2;
                asm("mov.b64 %0, {%1, %1};" : "=l"(tv2) : "r"(__float_as_uint(vv[j])));
                const unsigned long long* w2 =
                    (const unsigned long long*)(sWc + (t * FIN + j) * 64);
#pragma unroll
                for (int p = 0; p < 32; p++) {
                    unsigned long long wv = w2[p];
                    asm("fma.rn.f32x2 %0, %1, %2, %0;" : "+l"(acc[p]) : "l"(tv2), "l"(wv));
                }
            }
        }

        // gate + linear directly on accumulators: acc[p<16] -> Z cols 2p,2p+1;
        // acc[p>=16] -> H~ cols.
#pragma unroll
        for (int p = 0; p < 16; p++) {
            unsigned zlo = (unsigned)(acc[p] & 0xffffffffu);
            unsigned zhi = (unsigned)(acc[p] >> 32);
            unsigned hlo = (unsigned)(acc[p + 16] & 0xffffffffu);
            unsigned hhi = (unsigned)(acc[p + 16] >> 32);
            int f0 = 2 * p, f1 = 2 * p + 1;
            float z0 = 1.0f / (1.0f + expf(-(__uint_as_float(zlo) + sBz[f0])));
            float z1 = 1.0f / (1.0f + expf(-(__uint_as_float(zhi) + sBz[f1])));
            float h0 = tanhf(__uint_as_float(hlo) + sBh[f0]);
            float h1 = tanhf(__uint_as_float(hhi) + sBh[f1]);
            float v0 = fmaxf((1.0f - z0) * h0, 0.0f);
            float v1 = fmaxf((1.0f - z1) * h1, 0.0f);
            y0 += v0 * sWl[f0 * 4 + 0] + v1 * sWl[f1 * 4 + 0];
            y1 += v0 * sWl[f0 * 4 + 1] + v1 * sWl[f1 * 4 + 1];
            y2 += v0 * sWl[f0 * 4 + 2] + v1 * sWl[f1 * 4 + 2];
            y3 += v0 * sWl[f0 * 4 + 3] + v1 * sWl[f1 * 4 + 3];
        }
    }

    // warp-aggregated pooling (batch sorted: most warps see one graph id)
    int g0 = __shfl_sync(0xffffffffu, g, 0);
    bool uni = __all_sync(0xffffffffu, g == g0);
    if (uni) {
        if (g0 >= 0) {
#pragma unroll
            for (int off = 16; off > 0; off >>= 1) {
                y0   += __shfl_down_sync(0xffffffffu, y0, off);
                y1   += __shfl_down_sync(0xffffffffu, y1, off);
                y2   += __shfl_down_sync(0xffffffffu, y2, off);
                y3   += __shfl_down_sync(0xffffffffu, y3, off);
                cntv += __shfl_down_sync(0xffffffffu, cntv, off);
            }
            if ((threadIdx.x & 31) == 0) {
                atomicAdd(&d_gsum[g0 * 4 + 0], y0);
                atomicAdd(&d_gsum[g0 * 4 + 1], y1);
                atomicAdd(&d_gsum[g0 * 4 + 2], y2);
                atomicAdd(&d_gsum[g0 * 4 + 3], y3);
                atomicAdd(&d_gcnt[g0], cntv);
            }
        }
    } else if (g >= 0) {
        atomicAdd(&d_gsum[g * 4 + 0], y0);
        atomicAdd(&d_gsum[g * 4 + 1], y1);
        atomicAdd(&d_gsum[g * 4 + 2], y2);
        atomicAdd(&d_gsum[g * 4 + 3], y3);
        atomicAdd(&d_gcnt[g], cntv);
    }
}

__global__ void finalize_kernel(float* __restrict__ out, const float* __restrict__ bl, int G4) {
    int idx = blockIdx.x * blockDim.x + threadIdx.x;
    if (idx >= G4) return;
    int g = idx >> 2, c = idx & 3;
    out[idx] = d_gsum[idx] / d_gcnt[g] + bl[c];
}

// ---------------- host launch ----------------
extern "C" void kernel_launch(void* const* d_in, const int* in_sizes, int n_in,
                              void* d_out, int out_size) {
    const float* x     = (const float*)d_in[0];
    const int*   ei    = (const int*)  d_in[1];
    const float* w     = (const float*)d_in[2];
    const int*   batch = (const int*)  d_in[3];
    const float* Wz    = (const float*)d_in[4];
    const float* bz    = (const float*)d_in[5];
    // d_in[6]=W_r, d_in[7]=b_r unused (R gate multiplies the zero hidden state)
    const float* Wh    = (const float*)d_in[8];
    const float* bh    = (const float*)d_in[9];
    const float* Wl    = (const float*)d_in[10];
    const float* bl    = (const float*)d_in[11];
    float* out = (float*)d_out;

    int Nn = in_sizes[0] / FIN;        // 100000
    int E  = in_sizes[2];              // 1600000
    int Gg = out_size / 4;             // 100
    const int* row = ei;
    const int* col = ei + E;

    dim3 blk(256);
    int gNn  = (Nn + 255) / 256;
    int g4N  = (4 * Nn + 255) / 256;    // 2 threads per node-dir
    int gE2  = ((E + 1) / 2 + 255) / 256;   // 2 edges per thread

    static __half *hXpp = nullptr, *hSp = nullptr, *hTp = nullptr;
    if (!hXpp) {
        cudaGetSymbolAddress((void**)&hXpp, d_hXp);
        cudaGetSymbolAddress((void**)&hSp, d_hS);
        cudaGetSymbolAddress((void**)&hTp, d_hTi);
    }
    __half* hS0 = hSp;            __half* hS1 = hSp + HRSZ;     __half* hS2 = hSp + 2 * HRSZ;
    __half* hS3 = hSp + 3 * HRSZ; __half* hS4 = hSp + 4 * HRSZ;
    __half* hT1 = hTp;            __half* hT2 = hTp + HRSZ;
    __half* hT3 = hTp + 2 * HRSZ; __half* hT4 = hTp + 3 * HRSZ;

    init_wc_kernel<<<gNn, blk>>>(Wz, Wh, Nn, Gg);
    degrees_rank_kernel<<<gE2, blk>>>(row, col, w, E);
    prep_alloc_kernel<<<gNn, blk>>>(x, Nn);
    fill_kernel<<<gE2, blk>>>(row, col, E);

    // Chebyshev steps (fwd chain in scaled S-space, rev chain direct);
    // all chain state fp16; pair-coalesced gathers (1 wavefront per neighbor).
    gprop_kernel<<<g4N, blk>>>(hS0, nullptr, hS1,  hXpp, nullptr, hT1, 1.0f, Nn);
    gprop_kernel<<<g4N, blk>>>(hS1, hS0,     hS2,  hT1,  hXpp,    hT2, 2.0f, Nn);
    gprop_kernel<<<g4N, blk>>>(hS2, hS1,     hS3,  hT2,  hT1,     hT3, 2.0f, Nn);
    gprop_kernel<<<g4N, blk>>>(hS3, hS2,     hS4,  hT3,  hT2,     hT4, 2.0f, Nn);

    matmul_gate_pool_kernel<<<(Nn + 127) / 128, 128>>>(x, batch, bz, bh, Wl, Nn);
    finalize_kernel<<<(Gg * 4 + 255) / 256, blk>>>(out, bl, Gg * 4);
}

// round 15
// speedup vs baseline: 1.3100x; 1.3100x over previous
#include <cuda_runtime.h>
#include <cuda_fp16.h>
#include <math.h>

// ---------------- problem constants ----------------
#define MAXN   100000
#define MAXE   1600000
#define MAXG   128
#define FIN    12
#define HROW   16                 // fp16 chain row: 16 halves = 32B
#define NT     9                  // matmul terms: x, To1..4, Ti1..4
#define WCSZ   (NT * FIN * 64)    // combined weights (Z|H stacked on 64)
#define PADE   (MAXE + 4 * MAXN)  // padded edge-list bound
#define HRSZ   ((size_t)(MAXN + 1) * HROW)   // fp16 chain row block (+ sentinel)

// ---------------- device scratch (static, no allocs) ----------------
__device__ float2 d_dcout[MAXN];  // {weighted out-degree, out-count(float)}
__device__ float2 d_dcin[MAXN];   // {weighted in-degree,  in-count(float)}
__device__ float  d_doi[MAXN], d_dii[MAXN];
__device__ int    d_cnt_in[MAXN], d_cnt_out[MAXN];
__device__ int    d_off_in[MAXN], d_off_out[MAXN];
__device__ int    d_ctr_in, d_ctr_out;       // global bump allocators
__device__ int    d_rank_in[MAXE], d_rank_out[MAXE];
__device__ int    d_csc[PADE];    // grouped by dst: src indices  (fwd gather)
__device__ int    d_csr[PADE];    // grouped by src: dst indices  (rev gather)
__device__ __half d_hXp[HRSZ];    // fp16 x (+ zero sentinel row MAXN)
__device__ __half d_hS[5][HRSZ];  // fp16 scaled fwd chain S0..S4
__device__ __half d_hTi[4][HRSZ]; // fp16 rev chain Ti1..Ti4
__device__ float  d_Wc[WCSZ];
__device__ float  d_gsum[MAXG * 4];
__device__ float  d_gcnt[MAXG];

// ---------------- helpers ----------------
// vector atomic add WITH return: accumulates {deg, cnt} and yields old values
// (old cnt == this edge's rank within its node segment)
__device__ __forceinline__ float2 atom_add2_ret(float2* p, float a, float b) {
    float2 r;
    asm volatile("atom.global.add.v2.f32 {%0, %1}, [%2], {%3, %4};"
                 : "=f"(r.x), "=f"(r.y)
                 : "l"(__cvta_generic_to_global(p)), "f"(a), "f"(b)
                 : "memory");
    return r;
}

__device__ __forceinline__ void store_h_row(__half* hdst, int n, const float* v) {
    __half2 h0 = __floats2half2_rn(v[0], v[1]);
    __half2 h1 = __floats2half2_rn(v[2], v[3]);
    __half2 h2 = __floats2half2_rn(v[4], v[5]);
    __half2 h3 = __floats2half2_rn(v[6], v[7]);
    __half2 h4 = __floats2half2_rn(v[8], v[9]);
    __half2 h5 = __floats2half2_rn(v[10], v[11]);
    __half2 zz = __floats2half2_rn(0.f, 0.f);
    uint4 u0, u1;
    u0.x = *(unsigned*)&h0; u0.y = *(unsigned*)&h1; u0.z = *(unsigned*)&h2; u0.w = *(unsigned*)&h3;
    u1.x = *(unsigned*)&h4; u1.y = *(unsigned*)&h5; u1.z = *(unsigned*)&zz; u1.w = *(unsigned*)&zz;
    uint4* p = (uint4*)(hdst + (size_t)n * HROW);
    p[0] = u0; p[1] = u1;
}

// ---------------- kernels ----------------

// zero accumulators + fp16 sentinel rows + build combined weights (all fused)
__global__ void init_wc_kernel(const float* __restrict__ Wz, const float* __restrict__ Wh,
                               int Nn, int Gg) {
    int i = blockIdx.x * blockDim.x + threadIdx.x;
    if (i == 0) { d_ctr_in = 0; d_ctr_out = 0; }
    if (i < Nn) {
        d_dcout[i] = make_float2(0.f, 0.f);
        d_dcin[i]  = make_float2(0.f, 0.f);
    }
    if (i < Gg * 4) d_gsum[i] = 0.f;
    if (i < Gg)     d_gcnt[i] = 0.f;
    if (i < HROW) {                // zero fp16 sentinel rows (index MAXN)
        __half z = __float2half(0.f);
        d_hXp[(size_t)MAXN * HROW + i] = z;
#pragma unroll
        for (int k = 0; k < 5; k++) d_hS[k][(size_t)MAXN * HROW + i] = z;
#pragma unroll
        for (int k = 0; k < 4; k++) d_hTi[k][(size_t)MAXN * HROW + i] = z;
    }
    if (i < WCSZ) {
        int f2 = i & 63;
        int j  = (i >> 6) % FIN;
        int t  = i / (FIN * 64);
        const float* W = (f2 < 32) ? Wz : Wh;
        int f = f2 & 31;
        float v;
        if (t == 0)      v = W[0 * 1408 + j * 32 + f] + W[5 * 1408 + j * 32 + f];
        else if (t <= 4) v = W[(0 * 5 + t) * 1408 + j * 32 + f];
        else             v = W[(1 * 5 + (t - 4)) * 1408 + j * 32 + f];
        d_Wc[i] = v;
    }
}

// weighted degrees + counts + per-edge ranks in ONE vector atomic per
// edge-direction (2 L2 atomic ops per edge, total). 2 edges per thread.
__global__ void degrees_rank_kernel(const int* __restrict__ row, const int* __restrict__ col,
                                    const float* __restrict__ w, int E) {
    int t = blockIdx.x * blockDim.x + threadIdx.x;
    int e = t * 2;
    if (e + 1 < E) {
        int2   ss = *(const int2*)(row + e);
        int2   dd = *(const int2*)(col + e);
        float2 ww = *(const float2*)(w + e);
        float2 ro0 = atom_add2_ret(&d_dcout[ss.x], ww.x, 1.f);
        float2 ro1 = atom_add2_ret(&d_dcout[ss.y], ww.y, 1.f);
        float2 ri0 = atom_add2_ret(&d_dcin[dd.x],  ww.x, 1.f);
        float2 ri1 = atom_add2_ret(&d_dcin[dd.y],  ww.y, 1.f);
        *(int2*)(d_rank_in + e)  = make_int2(__float2int_rn(ri0.y), __float2int_rn(ri1.y));
        *(int2*)(d_rank_out + e) = make_int2(__float2int_rn(ro0.y), __float2int_rn(ro1.y));
    } else if (e < E) {
        int s = row[e], d = col[e];
        float we = w[e];
        float2 ro = atom_add2_ret(&d_dcout[s], we, 1.f);
        float2 ri = atom_add2_ret(&d_dcin[d],  we, 1.f);
        d_rank_in[e]  = __float2int_rn(ri.y);
        d_rank_out[e] = __float2int_rn(ro.y);
    }
}

// fused: per-node prep (inv degrees, fp16 x, fp16 S0) + CSR segment allocation
// via warp-aggregated atomic bump + sentinel padding (region disjoint from fill)
__global__ void prep_alloc_kernel(const float* __restrict__ x, int Nn) {
    int i = blockIdx.x * blockDim.x + threadIdx.x;
    int lane = threadIdx.x & 31;

    int ci = 0, co = 0;
    float degi = 1.f, dego = 1.f;
    if (i < Nn) {
        float2 din = d_dcin[i];
        float2 dou = d_dcout[i];
        ci = __float2int_rn(din.y);
        co = __float2int_rn(dou.y);
        degi = din.x;
        dego = dou.x;
    }
    int pi = (ci + 3) & ~3;
    int po = (co + 3) & ~3;

    // warp-inclusive scan of padded counts
    int inc_i = pi, inc_o = po;
#pragma unroll
    for (int s = 1; s < 32; s <<= 1) {
        int vi = __shfl_up_sync(0xffffffffu, inc_i, s);
        int vo = __shfl_up_sync(0xffffffffu, inc_o, s);
        if (lane >= s) { inc_i += vi; inc_o += vo; }
    }
    int tot_i = __shfl_sync(0xffffffffu, inc_i, 31);
    int tot_o = __shfl_sync(0xffffffffu, inc_o, 31);
    int base_i = 0, base_o = 0;
    if (lane == 0) {
        base_i = atomicAdd(&d_ctr_in, tot_i);
        base_o = atomicAdd(&d_ctr_out, tot_o);
    }
    base_i = __shfl_sync(0xffffffffu, base_i, 0);
    base_o = __shfl_sync(0xffffffffu, base_o, 0);

    if (i < Nn) {
        int oi = base_i + inc_i - pi;
        int oo = base_o + inc_o - po;
        d_off_in[i] = oi;  d_cnt_in[i] = ci;
        d_off_out[i] = oo; d_cnt_out[i] = co;

        // sentinel padding: [off+cnt, off+pad) never touched by fill
        for (int k = ci; k < pi; k++) d_csc[oi + k] = MAXN;
        for (int k = co; k < po; k++) d_csr[oo + k] = MAXN;

        float doi = 1.0f / dego;
        float dii = 1.0f / degi;
        d_doi[i] = doi; d_dii[i] = dii;

        float v[FIN], s0[FIN];
        const float4* xr = (const float4*)(x + (size_t)i * FIN);
        float4 a = xr[0], b = xr[1], c = xr[2];
        v[0]=a.x; v[1]=a.y; v[2]=a.z; v[3]=a.w;
        v[4]=b.x; v[5]=b.y; v[6]=b.z; v[7]=b.w;
        v[8]=c.x; v[9]=c.y; v[10]=c.z; v[11]=c.w;
#pragma unroll
        for (int j = 0; j < FIN; j++) s0[j] = v[j] * doi;
        store_h_row(d_hXp, i, v);
        store_h_row(d_hS[0], i, s0);
    }
}

// CSR/CSC fill with precomputed ranks — NO atomics: coalesced idx/rank loads,
// L2-cached off gathers, scattered stores only. 2 edges per thread.
__global__ void fill_kernel(const int* __restrict__ row, const int* __restrict__ col,
                            int E) {
    int t = blockIdx.x * blockDim.x + threadIdx.x;
    int e = t * 2;
    if (e + 1 < E) {
        int2 ss = *(const int2*)(row + e);
        int2 dd = *(const int2*)(col + e);
        int2 ri = *(const int2*)(d_rank_in + e);
        int2 ro = *(const int2*)(d_rank_out + e);
        int p0 = d_off_in[dd.x] + ri.x;
        int p1 = d_off_in[dd.y] + ri.y;
        int q0 = d_off_out[ss.x] + ro.x;
        int q1 = d_off_out[ss.y] + ro.y;
        d_csc[p0] = ss.x;
        d_csc[p1] = ss.y;
        d_csr[q0] = dd.x;
        d_csr[q1] = dd.y;
    } else if (e < E) {
        int s = row[e], d = col[e];
        d_csc[d_off_in[d] + d_rank_in[e]] = s;
        d_csr[d_off_out[s] + d_rank_out[e]] = d;
    }
}

// accumulate one int4 group (4 fp16 neighbor rows) into acc[6]
__device__ __forceinline__ void acc_group4(__half2 acc[6], const __half* __restrict__ hsrc,
                                           int4 q) {
    const uint4* r0 = (const uint4*)(hsrc + (size_t)q.x * HROW);
    const uint4* r1 = (const uint4*)(hsrc + (size_t)q.y * HROW);
    const uint4* r2 = (const uint4*)(hsrc + (size_t)q.z * HROW);
    const uint4* r3 = (const uint4*)(hsrc + (size_t)q.w * HROW);
    uint4 A0 = r0[0], A1 = r0[1];
    uint4 B0 = r1[0], B1 = r1[1];
    uint4 C0 = r2[0], C1 = r2[1];
    uint4 D0 = r3[0], D1 = r3[1];
#define H2(u) (*reinterpret_cast<const __half2*>(&(u)))
    acc[0] = __hadd2(acc[0], H2(A0.x)); acc[1] = __hadd2(acc[1], H2(A0.y));
    acc[2] = __hadd2(acc[2], H2(A0.z)); acc[3] = __hadd2(acc[3], H2(A0.w));
    acc[4] = __hadd2(acc[4], H2(A1.x)); acc[5] = __hadd2(acc[5], H2(A1.y));
    acc[0] = __hadd2(acc[0], H2(B0.x)); acc[1] = __hadd2(acc[1], H2(B0.y));
    acc[2] = __hadd2(acc[2], H2(B0.z)); acc[3] = __hadd2(acc[3], H2(B0.w));
    acc[4] = __hadd2(acc[4], H2(B1.x)); acc[5] = __hadd2(acc[5], H2(B1.y));
    acc[0] = __hadd2(acc[0], H2(C0.x)); acc[1] = __hadd2(acc[1], H2(C0.y));
    acc[2] = __hadd2(acc[2], H2(C0.z)); acc[3] = __hadd2(acc[3], H2(C0.w));
    acc[4] = __hadd2(acc[4], H2(C1.x)); acc[5] = __hadd2(acc[5], H2(C1.y));
    acc[0] = __hadd2(acc[0], H2(D0.x)); acc[1] = __hadd2(acc[1], H2(D0.y));
    acc[2] = __hadd2(acc[2], H2(D0.z)); acc[3] = __hadd2(acc[3], H2(D0.w));
    acc[4] = __hadd2(acc[4], H2(D1.x)); acc[5] = __hadd2(acc[5], H2(D1.y));
#undef H2
}

// one gather side (thread-per-node), all-fp16 chain state:
//   out[n] = fac*diag[n]*sum_{edges(n)} hsrc[idx] - hprev[n];  fp16 store only
__device__ __forceinline__ void gather_side(
    int n, const int* __restrict__ idxbuf,
    const int* __restrict__ off, const int* __restrict__ cnt,
    const float* __restrict__ diag,
    const __half* __restrict__ hsrc, const __half* __restrict__ hprev,
    __half* __restrict__ hdst, float fac)
{
    __half2 acc[6];
    __half2 hz = __floats2half2_rn(0.f, 0.f);
#pragma unroll
    for (int p = 0; p < 6; p++) acc[p] = hz;

    int b = off[n];
    int e = b + ((cnt[n] + 3) & ~3);
    int i = b;
    for (; i + 8 <= e; i += 8) {
        int4 qa = *(const int4*)(idxbuf + i);
        int4 qb = *(const int4*)(idxbuf + i + 4);
        acc_group4(acc, hsrc, qa);
        acc_group4(acc, hsrc, qb);
    }
    if (i < e) {
        int4 qa = *(const int4*)(idxbuf + i);
        acc_group4(acc, hsrc, qa);
    }

    float c = diag[n] * fac;
    float out[FIN];
#pragma unroll
    for (int p = 0; p < 6; p++) {
        float2 f = __half22float2(acc[p]);
        out[2 * p]     = c * f.x;
        out[2 * p + 1] = c * f.y;
    }
    if (hprev) {
        const uint4* pp = (const uint4*)(hprev + (size_t)n * HROW);
        uint4 u0 = pp[0], u1 = pp[1];
#define H2(u) (*reinterpret_cast<const __half2*>(&(u)))
        float2 p0 = __half22float2(H2(u0.x));
        float2 p1 = __half22float2(H2(u0.y));
        float2 p2 = __half22float2(H2(u0.z));
        float2 p3 = __half22float2(H2(u0.w));
        float2 p4 = __half22float2(H2(u1.x));
        float2 p5 = __half22float2(H2(u1.y));
#undef H2
        out[0] -= p0.x; out[1] -= p0.y; out[2]  -= p1.x; out[3]  -= p1.y;
        out[4] -= p2.x; out[5] -= p2.y; out[6]  -= p3.x; out[7]  -= p3.y;
        out[8] -= p4.x; out[9] -= p4.y; out[10] -= p5.x; out[11] -= p5.y;
    }
    store_h_row(hdst, n, out);
}

// one Chebyshev step, both chains; threads [0,N) fwd, [N,2N) rev
__global__ __launch_bounds__(256) void gprop_kernel(
    const __half* __restrict__ hsF, const __half* __restrict__ hpF, __half* __restrict__ hdF,
    const __half* __restrict__ hsR, const __half* __restrict__ hpR, __half* __restrict__ hdR,
    float fac, int Nn)
{
    int tid = blockIdx.x * blockDim.x + threadIdx.x;
    if (tid < Nn) {
        gather_side(tid, d_csc, d_off_in, d_cnt_in, d_doi, hsF, hpF, hdF, fac);
    } else if (tid < 2 * Nn) {
        gather_side(tid - Nn, d_csr, d_off_out, d_cnt_out, d_dii, hsR, hpR, hdR, fac);
    }
}

// fused: H = x@Wc0 + sum_k (dout*S_k)@Wc_k + sum_k Ti_k@Wc_{4+k} (fp16 chains),
// then GRU gate (zero hidden) + relu + 32x4 linear + warp-aggregated mean-pool.
__global__ __launch_bounds__(128) void matmul_gate_pool_kernel(
    const float* __restrict__ x, const int* __restrict__ batch,
    const float* __restrict__ bz, const float* __restrict__ bh,
    const float* __restrict__ Wl, int Nn)
{
    __shared__ float sWc[WCSZ];
    __shared__ float sBz[32], sBh[32], sWl[128];
    for (int i = threadIdx.x; i < WCSZ; i += blockDim.x) sWc[i] = d_Wc[i];
    if (threadIdx.x < 32)  sBz[threadIdx.x] = bz[threadIdx.x];
    else if (threadIdx.x < 64) sBh[threadIdx.x - 32] = bh[threadIdx.x - 32];
    if (threadIdx.x < 128) sWl[threadIdx.x] = Wl[threadIdx.x];
    __syncthreads();

    int n = blockIdx.x * blockDim.x + threadIdx.x;
    float y0 = 0.f, y1 = 0.f, y2 = 0.f, y3 = 0.f, cntv = 0.f;
    int g = -1;

    if (n < Nn) {
        g = batch[n];
        cntv = 1.f;
        float dout = d_dcout[n].x;

        unsigned long long acc[32];
#pragma unroll
        for (int p = 0; p < 32; p++) acc[p] = 0ULL;

#pragma unroll 1
        for (int t = 0; t < NT; t++) {
            float vv[FIN];
            if (t == 0) {
                const float4* src = (const float4*)(x + (size_t)n * FIN);
                float4 v0 = src[0], v1 = src[1], v2 = src[2];
                vv[0]=v0.x; vv[1]=v0.y; vv[2]=v0.z; vv[3]=v0.w;
                vv[4]=v1.x; vv[5]=v1.y; vv[6]=v1.z; vv[7]=v1.w;
                vv[8]=v2.x; vv[9]=v2.y; vv[10]=v2.z; vv[11]=v2.w;
            } else {
                const __half* hr = ((t <= 4) ? d_hS[t] : d_hTi[t - 5]) + (size_t)n * HROW;
                float scale = (t <= 4) ? dout : 1.0f;
                const uint4* pp = (const uint4*)hr;
                uint4 u0 = pp[0], u1 = pp[1];
#define H2(u) (*reinterpret_cast<const __half2*>(&(u)))
                float2 f0 = __half22float2(H2(u0.x));
                float2 f1 = __half22float2(H2(u0.y));
                float2 f2 = __half22float2(H2(u0.z));
                float2 f3 = __half22float2(H2(u0.w));
                float2 f4 = __half22float2(H2(u1.x));
                float2 f5 = __half22float2(H2(u1.y));
#undef H2
                vv[0]=f0.x*scale; vv[1]=f0.y*scale; vv[2]=f1.x*scale;  vv[3]=f1.y*scale;
                vv[4]=f2.x*scale; vv[5]=f2.y*scale; vv[6]=f3.x*scale;  vv[7]=f3.y*scale;
                vv[8]=f4.x*scale; vv[9]=f4.y*scale; vv[10]=f5.x*scale; vv[11]=f5.y*scale;
            }
#pragma unroll
            for (int j = 0; j < FIN; j++) {
                unsigned long long tv2;
                asm("mov.b64 %0, {%1, %1};" : "=l"(tv2) : "r"(__float_as_uint(vv[j])));
                const unsigned long long* w2 =
                    (const unsigned long long*)(sWc + (t * FIN + j) * 64);
#pragma unroll
                for (int p = 0; p < 32; p++) {
                    unsigned long long wv = w2[p];
                    asm("fma.rn.f32x2 %0, %1, %2, %0;" : "+l"(acc[p]) : "l"(tv2), "l"(wv));
                }
            }
        }

        // gate + linear directly on accumulators: acc[p<16] -> Z cols 2p,2p+1;
        // acc[p>=16] -> H~ cols.
#pragma unroll
        for (int p = 0; p < 16; p++) {
            unsigned zlo = (unsigned)(acc[p] & 0xffffffffu);
            unsigned zhi = (unsigned)(acc[p] >> 32);
            unsigned hlo = (unsigned)(acc[p + 16] & 0xffffffffu);
            unsigned hhi = (unsigned)(acc[p + 16] >> 32);
            int f0 = 2 * p, f1 = 2 * p + 1;
            float z0 = 1.0f / (1.0f + expf(-(__uint_as_float(zlo) + sBz[f0])));
            float z1 = 1.0f / (1.0f + expf(-(__uint_as_float(zhi) + sBz[f1])));
            float h0 = tanhf(__uint_as_float(hlo) + sBh[f0]);
            float h1 = tanhf(__uint_as_float(hhi) + sBh[f1]);
            float v0 = fmaxf((1.0f - z0) * h0, 0.0f);
            float v1 = fmaxf((1.0f - z1) * h1, 0.0f);
            y0 += v0 * sWl[f0 * 4 + 0] + v1 * sWl[f1 * 4 + 0];
            y1 += v0 * sWl[f0 * 4 + 1] + v1 * sWl[f1 * 4 + 1];
            y2 += v0 * sWl[f0 * 4 + 2] + v1 * sWl[f1 * 4 + 2];
            y3 += v0 * sWl[f0 * 4 + 3] + v1 * sWl[f1 * 4 + 3];
        }
    }

    // warp-aggregated pooling (batch sorted: most warps see one graph id)
    int g0 = __shfl_sync(0xffffffffu, g, 0);
    bool uni = __all_sync(0xffffffffu, g == g0);
    if (uni) {
        if (g0 >= 0) {
#pragma unroll
            for (int off = 16; off > 0; off >>= 1) {
                y0   += __shfl_down_sync(0xffffffffu, y0, off);
                y1   += __shfl_down_sync(0xffffffffu, y1, off);
                y2   += __shfl_down_sync(0xffffffffu, y2, off);
                y3   += __shfl_down_sync(0xffffffffu, y3, off);
                cntv += __shfl_down_sync(0xffffffffu, cntv, off);
            }
            if ((threadIdx.x & 31) == 0) {
                atomicAdd(&d_gsum[g0 * 4 + 0], y0);
                atomicAdd(&d_gsum[g0 * 4 + 1], y1);
                atomicAdd(&d_gsum[g0 * 4 + 2], y2);
                atomicAdd(&d_gsum[g0 * 4 + 3], y3);
                atomicAdd(&d_gcnt[g0], cntv);
            }
        }
    } else if (g >= 0) {
        atomicAdd(&d_gsum[g * 4 + 0], y0);
        atomicAdd(&d_gsum[g * 4 + 1], y1);
        atomicAdd(&d_gsum[g * 4 + 2], y2);
        atomicAdd(&d_gsum[g * 4 + 3], y3);
        atomicAdd(&d_gcnt[g], cntv);
    }
}

__global__ void finalize_kernel(float* __restrict__ out, const float* __restrict__ bl, int G4) {
    int idx = blockIdx.x * blockDim.x + threadIdx.x;
    if (idx >= G4) return;
    int g = idx >> 2, c = idx & 3;
    out[idx] = d_gsum[idx] / d_gcnt[g] + bl[c];
}

// ---------------- host launch ----------------
extern "C" void kernel_launch(void* const* d_in, const int* in_sizes, int n_in,
                              void* d_out, int out_size) {
    const float* x     = (const float*)d_in[0];
    const int*   ei    = (const int*)  d_in[1];
    const float* w     = (const float*)d_in[2];
    const int*   batch = (const int*)  d_in[3];
    const float* Wz    = (const float*)d_in[4];
    const float* bz    = (const float*)d_in[5];
    // d_in[6]=W_r, d_in[7]=b_r unused (R gate multiplies the zero hidden state)
    const float* Wh    = (const float*)d_in[8];
    const float* bh    = (const float*)d_in[9];
    const float* Wl    = (const float*)d_in[10];
    const float* bl    = (const float*)d_in[11];
    float* out = (float*)d_out;

    int Nn = in_sizes[0] / FIN;        // 100000
    int E  = in_sizes[2];              // 1600000
    int Gg = out_size / 4;             // 100
    const int* row = ei;
    const int* col = ei + E;

    dim3 blk(256);
    int gNn  = (Nn + 255) / 256;
    int g2N  = (2 * Nn + 255) / 256;
    int gE2  = ((E + 1) / 2 + 255) / 256;   // 2 edges per thread

    static __half *hXpp = nullptr, *hSp = nullptr, *hTp = nullptr;
    if (!hXpp) {
        cudaGetSymbolAddress((void**)&hXpp, d_hXp);
        cudaGetSymbolAddress((void**)&hSp, d_hS);
        cudaGetSymbolAddress((void**)&hTp, d_hTi);
    }
    __half* hS0 = hSp;            __half* hS1 = hSp + HRSZ;     __half* hS2 = hSp + 2 * HRSZ;
    __half* hS3 = hSp + 3 * HRSZ; __half* hS4 = hSp + 4 * HRSZ;
    __half* hT1 = hTp;            __half* hT2 = hTp + HRSZ;
    __half* hT3 = hTp + 2 * HRSZ; __half* hT4 = hTp + 3 * HRSZ;

    init_wc_kernel<<<gNn, blk>>>(Wz, Wh, Nn, Gg);
    degrees_rank_kernel<<<gE2, blk>>>(row, col, w, E);
    prep_alloc_kernel<<<gNn, blk>>>(x, Nn);
    fill_kernel<<<gE2, blk>>>(row, col, E);

    // Chebyshev steps (fwd chain in scaled S-space, rev chain direct);
    // all chain state fp16: gathers, prev-subtract, and matmul inputs.
    gprop_kernel<<<g2N, blk>>>(hS0, nullptr, hS1,  hXpp, nullptr, hT1, 1.0f, Nn);
    gprop_kernel<<<g2N, blk>>>(hS1, hS0,     hS2,  hT1,  hXpp,    hT2, 2.0f, Nn);
    gprop_kernel<<<g2N, blk>>>(hS2, hS1,     hS3,  hT2,  hT1,     hT3, 2.0f, Nn);
    gprop_kernel<<<g2N, blk>>>(hS3, hS2,     hS4,  hT3,  hT2,     hT4, 2.0f, Nn);

    matmul_gate_pool_kernel<<<(Nn + 127) / 128, 128>>>(x, batch, bz, bh, Wl, Nn);
    finalize_kernel<<<(Gg * 4 + 255) / 256, blk>>>(out, bl, Gg * 4);
}